// round 12
// baseline (speedup 1.0000x reference)
#include <cuda_runtime.h>
#include <cuda_fp16.h>
#include <math.h>
#include <stdint.h>

#define BB 4
#define NN 4096
#define CC 256
#define L2E 1.4426950408889634f

typedef unsigned long long ull;
typedef unsigned int u32;

// ---------------- scratch (device globals; no allocation allowed) ----------
__device__ __half d_f16p[BB * NN * 64];                 // [n][0:32)=f_hi, [32:64)=f_lo
__device__ __half d_g16[BB * NN * 64];                  // [n][0:32)=g_hi, [32:64)=g_lo
__device__ __half d_h16T[(size_t)BB * CC * NN];         // [b][c][n]
__device__ float  d_o[(size_t)BB * NN * CC];            // attention out fp32
__device__ __half d_xhi[(size_t)BB * NN * CC];          // x hi plane
__device__ __half d_xlo[(size_t)BB * NN * CC];          // x lo plane
__device__ __half d_ohi[(size_t)BB * NN * CC];          // attn-out hi plane
__device__ __half d_olo[(size_t)BB * NN * CC];          // attn-out lo plane
__device__ __half d_Wfgh_hi[320 * 256];                 // [col][k]: 0-255 Wh, 256-287 Wf, 288-319 Wg
__device__ __half d_Wfgh_lo[320 * 256];
__device__ __half d_Wv_hi[256 * 256];
__device__ __half d_Wv_lo[256 * 256];

// ---------------- mma / cp.async / ldmatrix helpers --------------------------
__device__ __forceinline__ void mma16816(float* c, const u32* a, u32 b0, u32 b1) {
    asm volatile(
        "mma.sync.aligned.m16n8k16.row.col.f32.f16.f16.f32 "
        "{%0,%1,%2,%3}, {%4,%5,%6,%7}, {%8,%9}, {%0,%1,%2,%3};"
        : "+f"(c[0]), "+f"(c[1]), "+f"(c[2]), "+f"(c[3])
        : "r"(a[0]), "r"(a[1]), "r"(a[2]), "r"(a[3]), "r"(b0), "r"(b1));
}
__device__ __forceinline__ void ldsm4(u32& r0, u32& r1, u32& r2, u32& r3, u32 addr) {
    asm volatile("ldmatrix.sync.aligned.m8n8.x4.shared.b16 {%0,%1,%2,%3}, [%4];"
                 : "=r"(r0), "=r"(r1), "=r"(r2), "=r"(r3) : "r"(addr));
}
__device__ __forceinline__ u32 smem_u32(const void* p) {
    u32 a;
    asm("{ .reg .u64 t; cvta.to.shared.u64 t, %1; cvt.u32.u64 %0, t; }" : "=r"(a) : "l"(p));
    return a;
}
__device__ __forceinline__ void cpa16(u32 s, const void* g) {
    asm volatile("cp.async.cg.shared.global [%0], [%1], 16;" :: "r"(s), "l"(g));
}
#define CP_COMMIT() asm volatile("cp.async.commit_group;" ::: "memory")
#define CP_WAIT0()  asm volatile("cp.async.wait_group 0;" ::: "memory")
#define CP_WAIT1()  asm volatile("cp.async.wait_group 1;" ::: "memory")

__device__ __forceinline__ u32 f2h2u(float a, float b) {
    __half2 h = __floats2half2_rn(a, b);
    return *(u32*)&h;
}

// ===========================================================================
// Preconversion kernels
// ===========================================================================
__global__ __launch_bounds__(256) void k_wconv(
    const float* __restrict__ Wh, const float* __restrict__ Wf,
    const float* __restrict__ Wg, const float* __restrict__ Wv)
{
    const int k = blockIdx.x, t = threadIdx.x;
    float v = Wh[k * 256 + t];
    __half hi = __float2half_rn(v);
    d_Wfgh_hi[t * 256 + k] = hi;
    d_Wfgh_lo[t * 256 + k] = __float2half_rn(v - __half2float(hi));
    v = Wv[k * 256 + t];
    hi = __float2half_rn(v);
    d_Wv_hi[t * 256 + k] = hi;
    d_Wv_lo[t * 256 + k] = __float2half_rn(v - __half2float(hi));
    if (t < 32) {
        v = Wf[k * 32 + t];
        hi = __float2half_rn(v);
        d_Wfgh_hi[(256 + t) * 256 + k] = hi;
        d_Wfgh_lo[(256 + t) * 256 + k] = __float2half_rn(v - __half2float(hi));
        v = Wg[k * 32 + t];
        hi = __float2half_rn(v);
        d_Wfgh_hi[(288 + t) * 256 + k] = hi;
        d_Wfgh_lo[(288 + t) * 256 + k] = __float2half_rn(v - __half2float(hi));
    }
}

__global__ __launch_bounds__(256) void k_conv_planes(
    const float* __restrict__ src, __half* __restrict__ hip, __half* __restrict__ lop)
{
    const size_t i = ((size_t)blockIdx.x * 256 + threadIdx.x) * 4;
    float4 v = *(const float4*)&src[i];
    __half2 h0 = __floats2half2_rn(v.x, v.y);
    __half2 h1 = __floats2half2_rn(v.z, v.w);
    float2 r0 = __half22float2(h0), r1 = __half22float2(h1);
    __half2 l0 = __floats2half2_rn(v.x - r0.x, v.y - r0.y);
    __half2 l1 = __floats2half2_rn(v.z - r1.x, v.w - r1.y);
    uint2 uh; uh.x = *(u32*)&h0; uh.y = *(u32*)&h1;
    uint2 ul; ul.x = *(u32*)&l0; ul.y = *(u32*)&l1;
    *(uint2*)&hip[i] = uh;
    *(uint2*)&lop[i] = ul;
}

// ===========================================================================
// Projection mainloop (shared pattern): A hi/lo f16 planes, W hi/lo f16,
// all fragments via ldmatrix.  Stride 40 halves (80 B) — ldsm conflict-free.
// ===========================================================================
#define AST 80     // A smem row stride bytes
#define WST 80     // W smem col stride bytes

// ===========================================================================
// Fused f/g/h projection.  CTA = 64 rows, 320 threads.
// smem: A 4x5120 + W 4x25600 = 122880
// ===========================================================================
#define FGH_SMEM (4 * 5120 + 4 * 25600)

__global__ __launch_bounds__(320) void k_fgh(
    const float* __restrict__ bh, const float* __restrict__ bf,
    const float* __restrict__ bg)
{
    extern __shared__ __align__(16) char sm[];
    u32 sAhi[2] = { smem_u32(sm),         smem_u32(sm + 5120) };
    u32 sAlo[2] = { smem_u32(sm + 10240), smem_u32(sm + 15360) };
    u32 sWhi[2] = { smem_u32(sm + 20480), smem_u32(sm + 46080) };
    u32 sWlo[2] = { smem_u32(sm + 71680), smem_u32(sm + 97280) };

    const int tid = threadIdx.x, w = tid >> 5, lane = tid & 31;
    const int qr = lane >> 2, kq2 = (lane & 3) << 1;
    const int mat = lane >> 3, ln8 = lane & 7;
    const u32 aOff = (u32)((8 * (mat & 1) + ln8) * AST + (mat >> 1) * 16);   // A-operand
    const u32 wOff = (u32)((8 * (mat >> 1) + ln8) * WST + (mat & 1) * 16);   // B-operand
    const int row0 = blockIdx.x * 64;
    const char* xh = (const char*)(d_xhi + (size_t)row0 * 256);
    const char* xl = (const char*)(d_xlo + (size_t)row0 * 256);
    const char* whi = (const char*)d_Wfgh_hi;
    const char* wlo = (const char*)d_Wfgh_lo;

    float acc[4][4][4] = {};

    // preload stage 0
    if (tid < 256) {
#pragma unroll
        for (int i = 0; i < 2; i++) {
            int e = tid * 2 + i;                 // 0..511
            int plane = e >> 8, rem = e & 255;
            int r = rem >> 2, seg = rem & 3;
            cpa16((plane ? sAlo[0] : sAhi[0]) + r * AST + seg * 16,
                  (plane ? xl : xh) + (size_t)r * 512 + seg * 16);
        }
    }
#pragma unroll
    for (int j = 0; j < 4; j++) {
        cpa16(sWhi[0] + tid * WST + j * 16, whi + (size_t)tid * 512 + j * 16);
        cpa16(sWlo[0] + tid * WST + j * 16, wlo + (size_t)tid * 512 + j * 16);
    }
    CP_COMMIT();

    for (int s = 0; s < 8; s++) {
        __syncthreads();
        if (s < 7) {
            const int k1 = (s + 1) * 32;
            const int nb = (s + 1) & 1;
            if (tid < 256) {
#pragma unroll
                for (int i = 0; i < 2; i++) {
                    int e = tid * 2 + i;
                    int plane = e >> 8, rem = e & 255;
                    int r = rem >> 2, seg = rem & 3;
                    cpa16((plane ? sAlo[nb] : sAhi[nb]) + r * AST + seg * 16,
                          (plane ? xl : xh) + (size_t)r * 512 + k1 * 2 + seg * 16);
                }
            }
#pragma unroll
            for (int j = 0; j < 4; j++) {
                cpa16(sWhi[nb] + tid * WST + j * 16, whi + (size_t)tid * 512 + k1 * 2 + j * 16);
                cpa16(sWlo[nb] + tid * WST + j * 16, wlo + (size_t)tid * 512 + k1 * 2 + j * 16);
            }
        }
        CP_COMMIT();
        if (s < 7) { CP_WAIT1(); } else { CP_WAIT0(); }
        __syncthreads();

        const u32 ah = sAhi[s & 1], al = sAlo[s & 1];
        const u32 wh = sWhi[s & 1], wl = sWlo[s & 1];
#pragma unroll
        for (int kc = 0; kc < 2; kc++) {
            u32 AH[4][4], AL[4][4];
#pragma unroll
            for (int rg = 0; rg < 4; rg++) {
                u32 base = (u32)(rg * 16 * AST + kc * 32) + aOff;
                ldsm4(AH[rg][0], AH[rg][1], AH[rg][2], AH[rg][3], ah + base);
                ldsm4(AL[rg][0], AL[rg][1], AL[rg][2], AL[rg][3], al + base);
            }
#pragma unroll
            for (int pr = 0; pr < 2; pr++) {
                u32 base = (u32)((w * 32 + pr * 16) * WST + kc * 32) + wOff;
                u32 BH[4], BL[4];
                ldsm4(BH[0], BH[1], BH[2], BH[3], wh + base);
                ldsm4(BL[0], BL[1], BL[2], BL[3], wl + base);
#pragma unroll
                for (int h = 0; h < 2; h++) {
                    int nt = pr * 2 + h;
                    u32 bh0 = BH[2 * h], bh1 = BH[2 * h + 1];
                    u32 bl0 = BL[2 * h], bl1 = BL[2 * h + 1];
#pragma unroll
                    for (int rg = 0; rg < 4; rg++) {
                        mma16816(acc[rg][nt], AH[rg], bh0, bh1);
                        mma16816(acc[rg][nt], AL[rg], bh0, bh1);
                        mma16816(acc[rg][nt], AH[rg], bl0, bl1);
                    }
                }
            }
        }
    }
    __syncthreads();   // reuse smem for output staging

    if (w < 8) {
        __half* reg = (__half*)(sm + w * 4096);
#pragma unroll
        for (int nt = 0; nt < 4; nt++) {
            int cl = nt * 8 + kq2;
            float b0 = bh[w * 32 + cl], b1 = bh[w * 32 + cl + 1];
#pragma unroll
            for (int rg = 0; rg < 4; rg++) {
                int r = rg * 16 + qr;
                __half2 p0 = __floats2half2_rn(acc[rg][nt][0] + b0, acc[rg][nt][1] + b1);
                __half2 p1 = __floats2half2_rn(acc[rg][nt][2] + b0, acc[rg][nt][3] + b1);
                reg[cl * 64 + r]           = __low2half(p0);
                reg[(cl + 1) * 64 + r]     = __high2half(p0);
                reg[cl * 64 + r + 8]       = __low2half(p1);
                reg[(cl + 1) * 64 + r + 8] = __high2half(p1);
            }
        }
        __syncwarp();
        const size_t b = (size_t)(row0 >> 12);
        const int nl = row0 & 4095;
        __half* dstb = d_h16T + b * (size_t)CC * NN;
#pragma unroll
        for (int i = 0; i < 8; i++) {
            int u = i * 32 + lane;
            int cl = u >> 3, seg = u & 7;
            *(uint4*)(dstb + (size_t)(w * 32 + cl) * NN + nl + seg * 8) =
                *(const uint4*)(reg + cl * 64 + seg * 8);
        }
    } else {
        __half* reg = (__half*)(sm + 32768 + (w - 8) * 8192);
        const float* bias = (w == 8) ? bf : bg;
#pragma unroll
        for (int nt = 0; nt < 4; nt++) {
            int cl = nt * 8 + kq2;
            float b0 = bias[cl], b1 = bias[cl + 1];
#pragma unroll
            for (int rg = 0; rg < 4; rg++) {
#pragma unroll
                for (int half = 0; half < 2; half++) {
                    int r = rg * 16 + qr + half * 8;
                    float v0 = acc[rg][nt][half * 2] + b0;
                    float v1 = acc[rg][nt][half * 2 + 1] + b1;
                    __half h0 = __float2half_rn(v0);
                    __half h1 = __float2half_rn(v1);
                    reg[r * 64 + cl] = h0;
                    reg[r * 64 + cl + 1] = h1;
                    reg[r * 64 + 32 + cl] = __float2half_rn(v0 - __half2float(h0));
                    reg[r * 64 + 32 + cl + 1] = __float2half_rn(v1 - __half2float(h1));
                }
            }
        }
        __syncwarp();
        __half* dst = ((w == 8) ? d_f16p : d_g16) + (size_t)row0 * 64;
#pragma unroll
        for (int i = 0; i < 16; i++) {
            int u = i * 32 + lane;
            int r = u >> 3, seg = u & 7;
            *(uint4*)(dst + (size_t)r * 64 + seg * 8) = *(const uint4*)(reg + r * 64 + seg * 8);
        }
    }
}

// ===========================================================================
// v projection + residual.  CTA = 64 rows, 256 threads.  A = d_ohi/d_olo.
// smem: A 4x5120 + W 4x20480 = 102400
// ===========================================================================
#define VP_SMEM (4 * 5120 + 4 * 20480)

__global__ __launch_bounds__(256) void k_vproj(
    const float* __restrict__ bv, const float* __restrict__ x, float* __restrict__ out)
{
    extern __shared__ __align__(16) char sm[];
    u32 sAhi[2] = { smem_u32(sm),         smem_u32(sm + 5120) };
    u32 sAlo[2] = { smem_u32(sm + 10240), smem_u32(sm + 15360) };
    u32 sWhi[2] = { smem_u32(sm + 20480), smem_u32(sm + 40960) };
    u32 sWlo[2] = { smem_u32(sm + 61440), smem_u32(sm + 81920) };

    const int tid = threadIdx.x, w = tid >> 5, lane = tid & 31;
    const int qr = lane >> 2, kq2 = (lane & 3) << 1;
    const int mat = lane >> 3, ln8 = lane & 7;
    const u32 aOff = (u32)((8 * (mat & 1) + ln8) * AST + (mat >> 1) * 16);
    const u32 wOff = (u32)((8 * (mat >> 1) + ln8) * WST + (mat & 1) * 16);
    const int row0 = blockIdx.x * 64;
    const char* ah0p = (const char*)(d_ohi + (size_t)row0 * 256);
    const char* al0p = (const char*)(d_olo + (size_t)row0 * 256);
    const char* whi = (const char*)d_Wv_hi;
    const char* wlo = (const char*)d_Wv_lo;

    float acc[4][4][4] = {};

#pragma unroll
    for (int i = 0; i < 2; i++) {
        int e = tid * 2 + i;
        int plane = e >> 8, rem = e & 255;
        int r = rem >> 2, seg = rem & 3;
        cpa16((plane ? sAlo[0] : sAhi[0]) + r * AST + seg * 16,
              (plane ? al0p : ah0p) + (size_t)r * 512 + seg * 16);
    }
#pragma unroll
    for (int j = 0; j < 4; j++) {
        cpa16(sWhi[0] + tid * WST + j * 16, whi + (size_t)tid * 512 + j * 16);
        cpa16(sWlo[0] + tid * WST + j * 16, wlo + (size_t)tid * 512 + j * 16);
    }
    CP_COMMIT();

    for (int s = 0; s < 8; s++) {
        __syncthreads();
        if (s < 7) {
            const int k1 = (s + 1) * 32;
            const int nb = (s + 1) & 1;
#pragma unroll
            for (int i = 0; i < 2; i++) {
                int e = tid * 2 + i;
                int plane = e >> 8, rem = e & 255;
                int r = rem >> 2, seg = rem & 3;
                cpa16((plane ? sAlo[nb] : sAhi[nb]) + r * AST + seg * 16,
                      (plane ? al0p : ah0p) + (size_t)r * 512 + k1 * 2 + seg * 16);
            }
#pragma unroll
            for (int j = 0; j < 4; j++) {
                cpa16(sWhi[nb] + tid * WST + j * 16, whi + (size_t)tid * 512 + k1 * 2 + j * 16);
                cpa16(sWlo[nb] + tid * WST + j * 16, wlo + (size_t)tid * 512 + k1 * 2 + j * 16);
            }
        }
        CP_COMMIT();
        if (s < 7) { CP_WAIT1(); } else { CP_WAIT0(); }
        __syncthreads();

        const u32 ah = sAhi[s & 1], al = sAlo[s & 1];
        const u32 wh = sWhi[s & 1], wl = sWlo[s & 1];
#pragma unroll
        for (int kc = 0; kc < 2; kc++) {
            u32 AH[4][4], AL[4][4];
#pragma unroll
            for (int rg = 0; rg < 4; rg++) {
                u32 base = (u32)(rg * 16 * AST + kc * 32) + aOff;
                ldsm4(AH[rg][0], AH[rg][1], AH[rg][2], AH[rg][3], ah + base);
                ldsm4(AL[rg][0], AL[rg][1], AL[rg][2], AL[rg][3], al + base);
            }
#pragma unroll
            for (int pr = 0; pr < 2; pr++) {
                u32 base = (u32)((w * 32 + pr * 16) * WST + kc * 32) + wOff;
                u32 BH[4], BL[4];
                ldsm4(BH[0], BH[1], BH[2], BH[3], wh + base);
                ldsm4(BL[0], BL[1], BL[2], BL[3], wl + base);
#pragma unroll
                for (int h = 0; h < 2; h++) {
                    int nt = pr * 2 + h;
                    u32 bh0 = BH[2 * h], bh1 = BH[2 * h + 1];
                    u32 bl0 = BL[2 * h], bl1 = BL[2 * h + 1];
#pragma unroll
                    for (int rg = 0; rg < 4; rg++) {
                        mma16816(acc[rg][nt], AH[rg], bh0, bh1);
                        mma16816(acc[rg][nt], AL[rg], bh0, bh1);
                        mma16816(acc[rg][nt], AH[rg], bl0, bl1);
                    }
                }
            }
        }
    }

#pragma unroll
    for (int nt = 0; nt < 4; nt++) {
        int c = w * 32 + nt * 8 + kq2;
        float b0 = bv[c], b1 = bv[c + 1];
#pragma unroll
        for (int rg = 0; rg < 4; rg++) {
#pragma unroll
            for (int half = 0; half < 2; half++) {
                int r = row0 + rg * 16 + qr + half * 8;
                float2 xr = *(const float2*)&x[(size_t)r * 256 + c];
                float2 o;
                o.x = acc[rg][nt][half * 2] + b0 + xr.x;
                o.y = acc[rg][nt][half * 2 + 1] + b1 + xr.y;
                *(float2*)&out[(size_t)r * 256 + c] = o;
            }
        }
    }
}

// ===========================================================================
// HMMA flash attention — byte-identical to the measured R11 kernel.
// ===========================================================================
#define SF_STRIDE 144
#define SH_STRIDE 272
#define SF_BYTES (128 * SF_STRIDE)
#define SH_BYTES (256 * SH_STRIDE)
#define ATTN_SMEM (2 * SF_BYTES + 2 * SH_BYTES)
#define ONES_H2 0x3C003C00u

__global__ __launch_bounds__(256) void k_attn()
{
    extern __shared__ __align__(16) char dsm[];
    char* sFp[2] = { dsm, dsm + SF_BYTES };
    u32 sFu[2] = { smem_u32(sFp[0]), smem_u32(sFp[1]) };
    u32 sHu[2] = { smem_u32(dsm + 2 * SF_BYTES), smem_u32(dsm + 2 * SF_BYTES + SH_BYTES) };

    const int tid = threadIdx.x;
    const int w = tid >> 5, lane = tid & 31;
    const int qr = lane >> 2;
    const int kq = (lane & 3) << 1;
    const int b = blockIdx.y, q0 = blockIdx.x * 128;

    const int mat = lane >> 3, ln8 = lane & 7;
    const u32 fOffLane = (u32)((8 * (mat >> 1) + ln8) * SF_STRIDE + (mat & 1) * 16);
    const u32 hOffLane = (u32)((8 * (mat >> 1) + ln8) * SH_STRIDE + (mat & 1) * 16);
    const u32 pAOffLane = (u32)(ln8 * SF_STRIDE + mat * 16);

    const char* fglob = (const char*)(d_f16p + (size_t)b * NN * 64);
    const char* hglob = (const char*)(d_h16T + (size_t)b * CC * NN);

    u32 Ghi[2][4], Glo[2][4];
    {
        const char* g0 = (const char*)(d_g16 + (size_t)(b * NN + q0 + 16 * w) * 64);
#pragma unroll
        for (int c = 0; c < 2; ++c) {
            int kb = 16 * c + kq;
            Ghi[c][0] = *(const u32*)(g0 + (size_t)qr * 128 + kb * 2);
            Ghi[c][1] = *(const u32*)(g0 + (size_t)(qr + 8) * 128 + kb * 2);
            Ghi[c][2] = *(const u32*)(g0 + (size_t)qr * 128 + (kb + 8) * 2);
            Ghi[c][3] = *(const u32*)(g0 + (size_t)(qr + 8) * 128 + (kb + 8) * 2);
            Glo[c][0] = *(const u32*)(g0 + (size_t)qr * 128 + 64 + kb * 2);
            Glo[c][1] = *(const u32*)(g0 + (size_t)(qr + 8) * 128 + 64 + kb * 2);
            Glo[c][2] = *(const u32*)(g0 + (size_t)qr * 128 + 64 + (kb + 8) * 2);
            Glo[c][3] = *(const u32*)(g0 + (size_t)(qr + 8) * 128 + 64 + (kb + 8) * 2);
        }
    }

    // ================= Pass A: row max (hi-only S) =================
    float mrow0 = -1e30f, mrow1 = -1e30f;
    {
#pragma unroll
        for (int i = 0; i < 4; i++) {
            int e = tid + 256 * i; int row = e >> 3, q = e & 7;
            cpa16(sFu[0] + row * SF_STRIDE + q * 16, fglob + row * 128 + q * 16);
        }
        CP_COMMIT();
    }
#pragma unroll 1
    for (int kt = 0; kt < 32; ++kt) {
        if (kt < 31) {
            const char* gb = fglob + (size_t)(kt + 1) * 16384;
            u32 sb = sFu[(kt + 1) & 1];
#pragma unroll
            for (int i = 0; i < 4; i++) {
                int e = tid + 256 * i; int row = e >> 3, q = e & 7;
                cpa16(sb + row * SF_STRIDE + q * 16, gb + row * 128 + q * 16);
            }
            CP_COMMIT();
            CP_WAIT1();
        } else {
            CP_WAIT0();
        }
        __syncthreads();
        const u32 fbu = sFu[kt & 1];
#pragma unroll
        for (int j = 0; j < 16; ++j) {
            float c4[4] = {0.f, 0.f, 0.f, 0.f};
            u32 r0, r1, r2, r3;
            ldsm4(r0, r1, r2, r3, fbu + (u32)(8 * j * SF_STRIDE) + pAOffLane);
            mma16816(c4, Ghi[0], r0, r1);
            mma16816(c4, Ghi[1], r2, r3);
            mrow0 = fmaxf(mrow0, fmaxf(c4[0], c4[1]));
            mrow1 = fmaxf(mrow1, fmaxf(c4[2], c4[3]));
        }
        __syncthreads();
    }
    mrow0 = fmaxf(mrow0, __shfl_xor_sync(0xffffffffu, mrow0, 1));
    mrow0 = fmaxf(mrow0, __shfl_xor_sync(0xffffffffu, mrow0, 2));
    mrow1 = fmaxf(mrow1, __shfl_xor_sync(0xffffffffu, mrow1, 1));
    mrow1 = fmaxf(mrow1, __shfl_xor_sync(0xffffffffu, mrow1, 2));
    const float mL0 = mrow0 * L2E, mL1 = mrow1 * L2E;

    // ================= Pass B =================
    float oa[32][4];
#pragma unroll
    for (int j = 0; j < 32; ++j) { oa[j][0] = oa[j][1] = oa[j][2] = oa[j][3] = 0.f; }
    float lacc[4] = {0.f, 0.f, 0.f, 0.f};

    {
#pragma unroll
        for (int i = 0; i < 4; i++) {
            int e = tid + 256 * i; int row = e >> 3, q = e & 7;
            cpa16(sFu[0] + row * SF_STRIDE + q * 16, fglob + row * 128 + q * 16);
        }
#pragma unroll
        for (int i = 0; i < 16; i++) {
            int e = tid + 256 * i; int row = e >> 4, q = e & 15;
            cpa16(sHu[0] + row * SH_STRIDE + q * 16, hglob + (size_t)row * 8192 + q * 16);
        }
        CP_COMMIT();
    }

#pragma unroll 1
    for (int kt = 0; kt < 32; ++kt) {
        if (kt < 31) {
            u32 sfb = sFu[(kt + 1) & 1], shb = sHu[(kt + 1) & 1];
            const char* gf = fglob + (size_t)(kt + 1) * 16384;
            const char* gh = hglob + (size_t)(kt + 1) * 256;
#pragma unroll
            for (int i = 0; i < 4; i++) {
                int e = tid + 256 * i; int row = e >> 3, q = e & 7;
                cpa16(sfb + row * SF_STRIDE + q * 16, gf + row * 128 + q * 16);
            }
#pragma unroll
            for (int i = 0; i < 16; i++) {
                int e = tid + 256 * i; int row = e >> 4, q = e & 15;
                cpa16(shb + row * SH_STRIDE + q * 16, gh + (size_t)row * 8192 + q * 16);
            }
            CP_COMMIT();
            CP_WAIT1();
        } else {
            CP_WAIT0();
        }
        __syncthreads();

        const u32 fbu = sFu[kt & 1];
        const u32 hbu = sHu[kt & 1];

#pragma unroll
        for (int kk = 0; kk < 8; ++kk) {
            float cA[4] = {0.f, 0.f, 0.f, 0.f};
            float cB[4] = {0.f, 0.f, 0.f, 0.f};
            const u32 fRow = fbu + (u32)(16 * kk * SF_STRIDE) + fOffLane;
#pragma unroll
            for (int c = 0; c < 2; ++c) {
                u32 ah0, ah1, bh0, bh1, al0, al1, bl0, bl1;
                ldsm4(ah0, ah1, bh0, bh1, fRow + 32 * c);
                ldsm4(al0, al1, bl0, bl1, fRow + 32 * c + 64);
                mma16816(cA, Ghi[c], ah0, ah1);
                mma16816(cB, Ghi[c], bh0, bh1);
                mma16816(cA, Glo[c], ah0, ah1);
                mma16816(cB, Glo[c], bh0, bh1);
                mma16816(cA, Ghi[c], al0, al1);
                mma16816(cB, Ghi[c], bl0, bl1);
            }
            u32 P[4];
            P[0] = f2h2u(exp2f(fmaf(cA[0], L2E, -mL0)), exp2f(fmaf(cA[1], L2E, -mL0)));
            P[1] = f2h2u(exp2f(fmaf(cA[2], L2E, -mL1)), exp2f(fmaf(cA[3], L2E, -mL1)));
            P[2] = f2h2u(exp2f(fmaf(cB[0], L2E, -mL0)), exp2f(fmaf(cB[1], L2E, -mL0)));
            P[3] = f2h2u(exp2f(fmaf(cB[2], L2E, -mL1)), exp2f(fmaf(cB[3], L2E, -mL1)));

            mma16816(lacc, P, ONES_H2, ONES_H2);

            const u32 hRow = hbu + (u32)(32 * kk) + hOffLane;
#pragma unroll
            for (int pr = 0; pr < 16; ++pr) {
                u32 r0, r1, r2, r3;
                ldsm4(r0, r1, r2, r3, hRow + (u32)(16 * pr * SH_STRIDE));
                mma16816(oa[2 * pr], P, r0, r1);
                mma16816(oa[2 * pr + 1], P, r2, r3);
            }
        }
        __syncthreads();
    }

    // ---- epilogue: o = O / li ----
    {
        float inv0 = 1.0f / lacc[0];
        float inv1 = 1.0f / lacc[2];
        float* op = d_o + ((size_t)b * NN + q0 + 16 * w) * 256;
#pragma unroll
        for (int j2 = 0; j2 < 32; ++j2) {
            int cc = 8 * j2 + kq;
            *(float2*)(op + (size_t)qr * 256 + cc) =
                make_float2(oa[j2][0] * inv0, oa[j2][1] * inv0);
            *(float2*)(op + (size_t)(qr + 8) * 256 + cc) =
                make_float2(oa[j2][2] * inv1, oa[j2][3] * inv1);
        }
    }
}

// ---------------------------------------------------------------------------
extern "C" void kernel_launch(void* const* d_in, const int* in_sizes, int n_in,
                              void* d_out, int out_size)
{
    const float* x  = (const float*)d_in[0];
    const float* Wf = (const float*)d_in[1];
    const float* bf = (const float*)d_in[2];
    const float* Wg = (const float*)d_in[3];
    const float* bg = (const float*)d_in[4];
    const float* Wh = (const float*)d_in[5];
    const float* bh = (const float*)d_in[6];
    const float* Wv = (const float*)d_in[7];
    const float* bv = (const float*)d_in[8];
    float* out = (float*)d_out;

    float* d_o_ptr;
    cudaGetSymbolAddress((void**)&d_o_ptr, d_o);
    __half *d_xhi_p, *d_xlo_p, *d_ohi_p, *d_olo_p;
    cudaGetSymbolAddress((void**)&d_xhi_p, d_xhi);
    cudaGetSymbolAddress((void**)&d_xlo_p, d_xlo);
    cudaGetSymbolAddress((void**)&d_ohi_p, d_ohi);
    cudaGetSymbolAddress((void**)&d_olo_p, d_olo);

    cudaFuncSetAttribute(k_fgh,   cudaFuncAttributeMaxDynamicSharedMemorySize, FGH_SMEM);
    cudaFuncSetAttribute(k_vproj, cudaFuncAttributeMaxDynamicSharedMemorySize, VP_SMEM);
    cudaFuncSetAttribute(k_attn,  cudaFuncAttributeMaxDynamicSharedMemorySize, ATTN_SMEM);

    k_wconv<<<256, 256>>>(Wh, Wf, Wg, Wv);
    k_conv_planes<<<4096, 256>>>(x, d_xhi_p, d_xlo_p);
    k_fgh<<<256, 320, FGH_SMEM>>>(bh, bf, bg);
    k_attn<<<dim3(32, 4), 256, ATTN_SMEM>>>();
    k_conv_planes<<<4096, 256>>>(d_o_ptr, d_ohi_p, d_olo_p);
    k_vproj<<<256, 256, VP_SMEM>>>(bv, x, out);
}

// round 13
// speedup vs baseline: 1.0719x; 1.0719x over previous
#include <cuda_runtime.h>
#include <cuda_fp16.h>
#include <math.h>
#include <stdint.h>

#define BB 4
#define NN 4096
#define CC 256
#define L2E 1.4426950408889634f

typedef unsigned long long ull;
typedef unsigned int u32;

// ---------------- scratch (device globals; no allocation allowed) ----------
__device__ __half d_f16p[BB * NN * 64];                 // [n][0:32)=f_hi, [32:64)=f_lo
__device__ __half d_g16[BB * NN * 64];                  // [n][0:32)=g_hi, [32:64)=g_lo
__device__ __half d_h16T[(size_t)BB * CC * NN];         // [b][c][n]
__device__ float  d_o[(size_t)BB * NN * CC];            // attention out fp32

// ---------------- mma / cp.async / ldmatrix helpers --------------------------
__device__ __forceinline__ void mma16816(float* c, const u32* a, u32 b0, u32 b1) {
    asm volatile(
        "mma.sync.aligned.m16n8k16.row.col.f32.f16.f16.f32 "
        "{%0,%1,%2,%3}, {%4,%5,%6,%7}, {%8,%9}, {%0,%1,%2,%3};"
        : "+f"(c[0]), "+f"(c[1]), "+f"(c[2]), "+f"(c[3])
        : "r"(a[0]), "r"(a[1]), "r"(a[2]), "r"(a[3]), "r"(b0), "r"(b1));
}
__device__ __forceinline__ void ldsm4(u32& r0, u32& r1, u32& r2, u32& r3, u32 addr) {
    asm volatile("ldmatrix.sync.aligned.m8n8.x4.shared.b16 {%0,%1,%2,%3}, [%4];"
                 : "=r"(r0), "=r"(r1), "=r"(r2), "=r"(r3) : "r"(addr));
}
__device__ __forceinline__ u32 smem_u32(const void* p) {
    u32 a;
    asm("{ .reg .u64 t; cvta.to.shared.u64 t, %1; cvt.u32.u64 %0, t; }" : "=r"(a) : "l"(p));
    return a;
}
__device__ __forceinline__ void cpa16(u32 s, const void* g) {
    asm volatile("cp.async.cg.shared.global [%0], [%1], 16;" :: "r"(s), "l"(g));
}
#define CP_COMMIT() asm volatile("cp.async.commit_group;" ::: "memory")
#define CP_WAIT0()  asm volatile("cp.async.wait_group 0;" ::: "memory")
#define CP_WAIT1()  asm volatile("cp.async.wait_group 1;" ::: "memory")

__device__ __forceinline__ u32 f2h2u(float a, float b) {
    __half2 h = __floats2half2_rn(a, b);
    return *(u32*)&h;
}

// ===========================================================================
// Fused f/g/h projection, HMMA 3-term.  CTA = 64 rows, 320 threads.
// (byte-identical to measured R11: 59.9 us)
// ===========================================================================
#define SA_STRIDE 40
#define SW_STRIDE 36
#define FGH_NCOL 320
#define FGH_SMEM (20480 + 2 * (FGH_NCOL * SW_STRIDE * 2))

__global__ __launch_bounds__(320) void k_fgh(
    const float* __restrict__ x,
    const float* __restrict__ Wh, const float* __restrict__ bh,
    const float* __restrict__ Wf, const float* __restrict__ bf,
    const float* __restrict__ Wg, const float* __restrict__ bg)
{
    extern __shared__ __align__(16) char sm[];
    float* sA[2] = { (float*)sm, (float*)(sm + 10240) };
    __half* sWhi = (__half*)(sm + 20480);
    __half* sWlo = (__half*)(sm + 20480 + FGH_NCOL * SW_STRIDE * 2);
    u32 sAu[2] = { smem_u32(sA[0]), smem_u32(sA[1]) };

    const int tid = threadIdx.x, w = tid >> 5, lane = tid & 31;
    const int qr = lane >> 2, kq2 = (lane & 3) << 1;
    const int row0 = blockIdx.x * 64;
    const char* xrow = (const char*)(x + (size_t)row0 * 256);

    float acc[4][4][4] = {};

    if (tid < 256) {
#pragma unroll
        for (int i = 0; i < 2; i++) {
            int e = tid * 2 + i; int r = e >> 3, s = e & 7;
            cpa16(sAu[0] + r * 160 + s * 16, xrow + (size_t)r * 1024 + s * 16);
        }
    }
    CP_COMMIT();

    for (int s = 0; s < 8; s++) {
        const int k0 = s * 32;
        __syncthreads();
        if (s < 7) {
            if (tid < 256) {
#pragma unroll
                for (int i = 0; i < 2; i++) {
                    int e = tid * 2 + i; int r = e >> 3, seg = e & 7;
                    cpa16(sAu[(s + 1) & 1] + r * 160 + seg * 16,
                          xrow + (size_t)r * 1024 + (k0 + 32) * 4 + seg * 16);
                }
            }
        }
        CP_COMMIT();
        {
            const float* wp; int stride;
            if (tid < 256)      { wp = Wh + tid;         stride = 256; }
            else if (tid < 288) { wp = Wf + (tid - 256); stride = 32; }
            else                { wp = Wg + (tid - 288); stride = 32; }
#pragma unroll
            for (int k = 0; k < 32; k++) {
                float v = wp[(size_t)(k0 + k) * stride];
                __half hi = __float2half_rn(v);
                sWhi[tid * SW_STRIDE + k] = hi;
                sWlo[tid * SW_STRIDE + k] = __float2half_rn(v - __half2float(hi));
            }
        }
        if (s < 7) { CP_WAIT1(); } else { CP_WAIT0(); }
        __syncthreads();

        const float* sa = sA[s & 1];
#pragma unroll
        for (int kc = 0; kc < 2; kc++) {
            u32 AH[4][4], AL[4][4];
#pragma unroll
            for (int rg = 0; rg < 4; rg++) {
                const float* base = sa + (rg * 16 + qr) * SA_STRIDE + kc * 16 + kq2;
                float2 v0 = *(const float2*)(base);
                float2 v1 = *(const float2*)(base + 8 * SA_STRIDE);
                float2 v2 = *(const float2*)(base + 8);
                float2 v3 = *(const float2*)(base + 8 * SA_STRIDE + 8);
                __half2 h;
                h = __floats2half2_rn(v0.x, v0.y); AH[rg][0] = *(u32*)&h;
                float2 r0 = __half22float2(h);
                h = __floats2half2_rn(v0.x - r0.x, v0.y - r0.y); AL[rg][0] = *(u32*)&h;
                h = __floats2half2_rn(v1.x, v1.y); AH[rg][1] = *(u32*)&h;
                float2 r1 = __half22float2(h);
                h = __floats2half2_rn(v1.x - r1.x, v1.y - r1.y); AL[rg][1] = *(u32*)&h;
                h = __floats2half2_rn(v2.x, v2.y); AH[rg][2] = *(u32*)&h;
                float2 r2 = __half22float2(h);
                h = __floats2half2_rn(v2.x - r2.x, v2.y - r2.y); AL[rg][2] = *(u32*)&h;
                h = __floats2half2_rn(v3.x, v3.y); AH[rg][3] = *(u32*)&h;
                float2 r3 = __half22float2(h);
                h = __floats2half2_rn(v3.x - r3.x, v3.y - r3.y); AL[rg][3] = *(u32*)&h;
            }
#pragma unroll
            for (int nt = 0; nt < 4; nt++) {
                const __half* bp  = sWhi + (w * 32 + nt * 8 + qr) * SW_STRIDE + kc * 16 + kq2;
                const __half* bpl = sWlo + (w * 32 + nt * 8 + qr) * SW_STRIDE + kc * 16 + kq2;
                u32 bh0 = *(const u32*)bp,  bh1 = *(const u32*)(bp + 8);
                u32 bl0 = *(const u32*)bpl, bl1 = *(const u32*)(bpl + 8);
#pragma unroll
                for (int rg = 0; rg < 4; rg++) {
                    mma16816(acc[rg][nt], AH[rg], bh0, bh1);
                    mma16816(acc[rg][nt], AL[rg], bh0, bh1);
                    mma16816(acc[rg][nt], AH[rg], bl0, bl1);
                }
            }
        }
    }
    __syncthreads();

    if (w < 8) {
        __half* reg = (__half*)(sm + w * 4096);
#pragma unroll
        for (int nt = 0; nt < 4; nt++) {
            int cl = nt * 8 + kq2;
            float b0 = bh[w * 32 + cl], b1 = bh[w * 32 + cl + 1];
#pragma unroll
            for (int rg = 0; rg < 4; rg++) {
                int r = rg * 16 + qr;
                __half2 p0 = __floats2half2_rn(acc[rg][nt][0] + b0, acc[rg][nt][1] + b1);
                __half2 p1 = __floats2half2_rn(acc[rg][nt][2] + b0, acc[rg][nt][3] + b1);
                reg[cl * 64 + r]           = __low2half(p0);
                reg[(cl + 1) * 64 + r]     = __high2half(p0);
                reg[cl * 64 + r + 8]       = __low2half(p1);
                reg[(cl + 1) * 64 + r + 8] = __high2half(p1);
            }
        }
        __syncwarp();
        const size_t b = (size_t)(row0 >> 12);
        const int nl = row0 & 4095;
        __half* dstb = d_h16T + b * (size_t)CC * NN;
#pragma unroll
        for (int i = 0; i < 8; i++) {
            int u = i * 32 + lane;
            int cl = u >> 3, seg = u & 7;
            *(uint4*)(dstb + (size_t)(w * 32 + cl) * NN + nl + seg * 8) =
                *(const uint4*)(reg + cl * 64 + seg * 8);
        }
    } else {
        __half* reg = (__half*)(sm + 32768 + (w - 8) * 8192);
        const float* bias = (w == 8) ? bf : bg;
#pragma unroll
        for (int nt = 0; nt < 4; nt++) {
            int cl = nt * 8 + kq2;
            float b0 = bias[cl], b1 = bias[cl + 1];
#pragma unroll
            for (int rg = 0; rg < 4; rg++) {
#pragma unroll
                for (int half = 0; half < 2; half++) {
                    int r = rg * 16 + qr + half * 8;
                    float v0 = acc[rg][nt][half * 2] + b0;
                    float v1 = acc[rg][nt][half * 2 + 1] + b1;
                    __half h0 = __float2half_rn(v0);
                    __half h1 = __float2half_rn(v1);
                    reg[r * 64 + cl] = h0;
                    reg[r * 64 + cl + 1] = h1;
                    reg[r * 64 + 32 + cl] = __float2half_rn(v0 - __half2float(h0));
                    reg[r * 64 + 32 + cl + 1] = __float2half_rn(v1 - __half2float(h1));
                }
            }
        }
        __syncwarp();
        __half* dst = ((w == 8) ? d_f16p : d_g16) + (size_t)row0 * 64;
#pragma unroll
        for (int i = 0; i < 16; i++) {
            int u = i * 32 + lane;
            int r = u >> 3, seg = u & 7;
            *(uint4*)(dst + (size_t)r * 64 + seg * 8) = *(const uint4*)(reg + r * 64 + seg * 8);
        }
    }
}

// ===========================================================================
// v projection + residual, HMMA 3-term (byte-identical to measured R11).
// ===========================================================================
#define VP_SMEM (20480 + 2 * (256 * SW_STRIDE * 2))

__global__ __launch_bounds__(256) void k_vproj(
    const float* __restrict__ Wv, const float* __restrict__ bv,
    const float* __restrict__ x, float* __restrict__ out)
{
    extern __shared__ __align__(16) char sm[];
    float* sA[2] = { (float*)sm, (float*)(sm + 10240) };
    __half* sWhi = (__half*)(sm + 20480);
    __half* sWlo = (__half*)(sm + 20480 + 256 * SW_STRIDE * 2);
    u32 sAu[2] = { smem_u32(sA[0]), smem_u32(sA[1]) };

    const int tid = threadIdx.x, w = tid >> 5, lane = tid & 31;
    const int qr = lane >> 2, kq2 = (lane & 3) << 1;
    const int row0 = blockIdx.x * 64;
    const char* arow = (const char*)(d_o + (size_t)row0 * 256);

    float acc[4][4][4] = {};

#pragma unroll
    for (int i = 0; i < 2; i++) {
        int e = tid * 2 + i; int r = e >> 3, s = e & 7;
        cpa16(sAu[0] + r * 160 + s * 16, arow + (size_t)r * 1024 + s * 16);
    }
    CP_COMMIT();

    for (int s = 0; s < 8; s++) {
        const int k0 = s * 32;
        __syncthreads();
        if (s < 7) {
#pragma unroll
            for (int i = 0; i < 2; i++) {
                int e = tid * 2 + i; int r = e >> 3, seg = e & 7;
                cpa16(sAu[(s + 1) & 1] + r * 160 + seg * 16,
                      arow + (size_t)r * 1024 + (k0 + 32) * 4 + seg * 16);
            }
        }
        CP_COMMIT();
        {
#pragma unroll
            for (int k = 0; k < 32; k++) {
                float v = Wv[(size_t)(k0 + k) * 256 + tid];
                __half hi = __float2half_rn(v);
                sWhi[tid * SW_STRIDE + k] = hi;
                sWlo[tid * SW_STRIDE + k] = __float2half_rn(v - __half2float(hi));
            }
        }
        if (s < 7) { CP_WAIT1(); } else { CP_WAIT0(); }
        __syncthreads();

        const float* sa = sA[s & 1];
#pragma unroll
        for (int kc = 0; kc < 2; kc++) {
            u32 AH[4][4], AL[4][4];
#pragma unroll
            for (int rg = 0; rg < 4; rg++) {
                const float* base = sa + (rg * 16 + qr) * SA_STRIDE + kc * 16 + kq2;
                float2 v0 = *(const float2*)(base);
                float2 v1 = *(const float2*)(base + 8 * SA_STRIDE);
                float2 v2 = *(const float2*)(base + 8);
                float2 v3 = *(const float2*)(base + 8 * SA_STRIDE + 8);
                __half2 h;
                h = __floats2half2_rn(v0.x, v0.y); AH[rg][0] = *(u32*)&h;
                float2 r0 = __half22float2(h);
                h = __floats2half2_rn(v0.x - r0.x, v0.y - r0.y); AL[rg][0] = *(u32*)&h;
                h = __floats2half2_rn(v1.x, v1.y); AH[rg][1] = *(u32*)&h;
                float2 r1 = __half22float2(h);
                h = __floats2half2_rn(v1.x - r1.x, v1.y - r1.y); AL[rg][1] = *(u32*)&h;
                h = __floats2half2_rn(v2.x, v2.y); AH[rg][2] = *(u32*)&h;
                float2 r2 = __half22float2(h);
                h = __floats2half2_rn(v2.x - r2.x, v2.y - r2.y); AL[rg][2] = *(u32*)&h;
                h = __floats2half2_rn(v3.x, v3.y); AH[rg][3] = *(u32*)&h;
                float2 r3 = __half22float2(h);
                h = __floats2half2_rn(v3.x - r3.x, v3.y - r3.y); AL[rg][3] = *(u32*)&h;
            }
#pragma unroll
            for (int nt = 0; nt < 4; nt++) {
                const __half* bp  = sWhi + (w * 32 + nt * 8 + qr) * SW_STRIDE + kc * 16 + kq2;
                const __half* bpl = sWlo + (w * 32 + nt * 8 + qr) * SW_STRIDE + kc * 16 + kq2;
                u32 bh0 = *(const u32*)bp,  bh1 = *(const u32*)(bp + 8);
                u32 bl0 = *(const u32*)bpl, bl1 = *(const u32*)(bpl + 8);
#pragma unroll
                for (int rg = 0; rg < 4; rg++) {
                    mma16816(acc[rg][nt], AH[rg], bh0, bh1);
                    mma16816(acc[rg][nt], AL[rg], bh0, bh1);
                    mma16816(acc[rg][nt], AH[rg], bl0, bl1);
                }
            }
        }
    }

#pragma unroll
    for (int nt = 0; nt < 4; nt++) {
        int c = w * 32 + nt * 8 + kq2;
        float b0 = bv[c], b1 = bv[c + 1];
#pragma unroll
        for (int rg = 0; rg < 4; rg++) {
#pragma unroll
            for (int half = 0; half < 2; half++) {
                int r = row0 + rg * 16 + qr + half * 8;
                float2 xr = *(const float2*)&x[(size_t)r * 256 + c];
                float2 o;
                o.x = acc[rg][nt][half * 2] + b0 + xr.x;
                o.y = acc[rg][nt][half * 2 + 1] + b1 + xr.y;
                *(float2*)&out[(size_t)r * 256 + c] = o;
            }
        }
    }
}

// ===========================================================================
// HMMA flash attention — R11 math, resized: CTA = 64 q rows (4 warps, 128
// threads), key-tile 64 -> smem 92160 B -> 2 CTAs/SM, grid 256 CTAs.
// ===========================================================================
#define SF_STRIDE 144
#define SH_STRIDE 144
#define SF_BYTES (64 * SF_STRIDE)      // 9216
#define SH_BYTES (256 * SH_STRIDE)     // 36864
#define ATTN_SMEM (2 * SF_BYTES + 2 * SH_BYTES)   // 92160
#define ONES_H2 0x3C003C00u

__global__ __launch_bounds__(128) void k_attn()
{
    extern __shared__ __align__(16) char dsm[];
    u32 sFu[2] = { smem_u32(dsm), smem_u32(dsm + SF_BYTES) };
    u32 sHu[2] = { smem_u32(dsm + 2 * SF_BYTES), smem_u32(dsm + 2 * SF_BYTES + SH_BYTES) };

    const int tid = threadIdx.x;
    const int w = tid >> 5, lane = tid & 31;
    const int qr = lane >> 2;
    const int kq = (lane & 3) << 1;
    const int b = blockIdx.y, q0 = blockIdx.x * 64;

    const int mat = lane >> 3, ln8 = lane & 7;
    const u32 fOffLane = (u32)((8 * (mat >> 1) + ln8) * SF_STRIDE + (mat & 1) * 16);
    const u32 hOffLane = (u32)((8 * (mat >> 1) + ln8) * SH_STRIDE + (mat & 1) * 16);
    const u32 pAOffLane = (u32)(ln8 * SF_STRIDE + mat * 16);

    const char* fglob = (const char*)(d_f16p + (size_t)b * NN * 64);
    const char* hglob = (const char*)(d_h16T + (size_t)b * CC * NN);

    u32 Ghi[2][4], Glo[2][4];
    {
        const char* g0 = (const char*)(d_g16 + (size_t)(b * NN + q0 + 16 * w) * 64);
#pragma unroll
        for (int c = 0; c < 2; ++c) {
            int kb = 16 * c + kq;
            Ghi[c][0] = *(const u32*)(g0 + (size_t)qr * 128 + kb * 2);
            Ghi[c][1] = *(const u32*)(g0 + (size_t)(qr + 8) * 128 + kb * 2);
            Ghi[c][2] = *(const u32*)(g0 + (size_t)qr * 128 + (kb + 8) * 2);
            Ghi[c][3] = *(const u32*)(g0 + (size_t)(qr + 8) * 128 + (kb + 8) * 2);
            Glo[c][0] = *(const u32*)(g0 + (size_t)qr * 128 + 64 + kb * 2);
            Glo[c][1] = *(const u32*)(g0 + (size_t)(qr + 8) * 128 + 64 + kb * 2);
            Glo[c][2] = *(const u32*)(g0 + (size_t)qr * 128 + 64 + (kb + 8) * 2);
            Glo[c][3] = *(const u32*)(g0 + (size_t)(qr + 8) * 128 + 64 + (kb + 8) * 2);
        }
    }

    // ================= Pass A: row max (hi-only S) =================
    float mrow0 = -1e30f, mrow1 = -1e30f;
    {
#pragma unroll
        for (int i = 0; i < 4; i++) {
            int e = tid + 128 * i; int row = e >> 3, q = e & 7;
            cpa16(sFu[0] + row * SF_STRIDE + q * 16, fglob + row * 128 + q * 16);
        }
        CP_COMMIT();
    }
#pragma unroll 1
    for (int kt = 0; kt < 64; ++kt) {
        if (kt < 63) {
            const char* gb = fglob + (size_t)(kt + 1) * 8192;
            u32 sb = sFu[(kt + 1) & 1];
#pragma unroll
            for (int i = 0; i < 4; i++) {
                int e = tid + 128 * i; int row = e >> 3, q = e & 7;
                cpa16(sb + row * SF_STRIDE + q * 16, gb + row * 128 + q * 16);
            }
            CP_COMMIT();
            CP_WAIT1();
        } else {
            CP_WAIT0();
        }
        __syncthreads();
        const u32 fbu = sFu[kt & 1];
#pragma unroll
        for (int j = 0; j < 8; ++j) {
            float c4[4] = {0.f, 0.f, 0.f, 0.f};
            u32 r0, r1, r2, r3;
            ldsm4(r0, r1, r2, r3, fbu + (u32)(8 * j * SF_STRIDE) + pAOffLane);
            mma16816(c4, Ghi[0], r0, r1);
            mma16816(c4, Ghi[1], r2, r3);
            mrow0 = fmaxf(mrow0, fmaxf(c4[0], c4[1]));
            mrow1 = fmaxf(mrow1, fmaxf(c4[2], c4[3]));
        }
        __syncthreads();
    }
    mrow0 = fmaxf(mrow0, __shfl_xor_sync(0xffffffffu, mrow0, 1));
    mrow0 = fmaxf(mrow0, __shfl_xor_sync(0xffffffffu, mrow0, 2));
    mrow1 = fmaxf(mrow1, __shfl_xor_sync(0xffffffffu, mrow1, 1));
    mrow1 = fmaxf(mrow1, __shfl_xor_sync(0xffffffffu, mrow1, 2));
    const float mL0 = mrow0 * L2E, mL1 = mrow1 * L2E;

    // ================= Pass B =================
    float oa[32][4];
#pragma unroll
    for (int j = 0; j < 32; ++j) { oa[j][0] = oa[j][1] = oa[j][2] = oa[j][3] = 0.f; }
    float lacc[4] = {0.f, 0.f, 0.f, 0.f};

    {
#pragma unroll
        for (int i = 0; i < 4; i++) {
            int e = tid + 128 * i; int row = e >> 3, q = e & 7;
            cpa16(sFu[0] + row * SF_STRIDE + q * 16, fglob + row * 128 + q * 16);
        }
#pragma unroll
        for (int i = 0; i < 16; i++) {
            int e = tid + 128 * i; int row = e >> 3, q = e & 7;
            cpa16(sHu[0] + row * SH_STRIDE + q * 16, hglob + (size_t)row * 8192 + q * 16);
        }
        CP_COMMIT();
    }

#pragma unroll 1
    for (int kt = 0; kt < 64; ++kt) {
        if (kt < 63) {
            u32 sfb = sFu[(kt + 1) & 1], shb = sHu[(kt + 1) & 1];
            const char* gf = fglob + (size_t)(kt + 1) * 8192;
            const char* gh = hglob + (size_t)(kt + 1) * 128;
#pragma unroll
            for (int i = 0; i < 4; i++) {
                int e = tid + 128 * i; int row = e >> 3, q = e & 7;
                cpa16(sfb + row * SF_STRIDE + q * 16, gf + row * 128 + q * 16);
            }
#pragma unroll
            for (int i = 0; i < 16; i++) {
                int e = tid + 128 * i; int row = e >> 3, q = e & 7;
                cpa16(shb + row * SH_STRIDE + q * 16, gh + (size_t)row * 8192 + q * 16);
            }
            CP_COMMIT();
            CP_WAIT1();
        } else {
            CP_WAIT0();
        }
        __syncthreads();

        const u32 fbu = sFu[kt & 1];
        const u32 hbu = sHu[kt & 1];

#pragma unroll
        for (int kk = 0; kk < 4; ++kk) {
            float cA[4] = {0.f, 0.f, 0.f, 0.f};
            float cB[4] = {0.f, 0.f, 0.f, 0.f};
            const u32 fRow = fbu + (u32)(16 * kk * SF_STRIDE) + fOffLane;
#pragma unroll
            for (int c = 0; c < 2; ++c) {
                u32 ah0, ah1, bh0, bh1, al0, al1, bl0, bl1;
                ldsm4(ah0, ah1, bh0, bh1, fRow + 32 * c);
                ldsm4(al0, al1, bl0, bl1, fRow + 32 * c + 64);
                mma16816(cA, Ghi[c], ah0, ah1);
                mma16816(cB, Ghi[c], bh0, bh1);
                mma16816(cA, Glo[c], ah0, ah1);
                mma16816(cB, Glo[c], bh0, bh1);
                mma16816(cA, Ghi[c], al0, al1);
                mma16816(cB, Ghi[c], bl0, bl1);
            }
            u32 P[4];
            P[0] = f2h2u(exp2f(fmaf(cA[0], L2E, -mL0)), exp2f(fmaf(cA[1], L2E, -mL0)));
            P[1] = f2h2u(exp2f(fmaf(cA[2], L2E, -mL1)), exp2f(fmaf(cA[3], L2E, -mL1)));
            P[2] = f2h2u(exp2f(fmaf(cB[0], L2E, -mL0)), exp2f(fmaf(cB[1], L2E, -mL0)));
            P[3] = f2h2u(exp2f(fmaf(cB[2], L2E, -mL1)), exp2f(fmaf(cB[3], L2E, -mL1)));

            mma16816(lacc, P, ONES_H2, ONES_H2);

            const u32 hRow = hbu + (u32)(32 * kk) + hOffLane;
#pragma unroll
            for (int pr = 0; pr < 16; ++pr) {
                u32 r0, r1, r2, r3;
                ldsm4(r0, r1, r2, r3, hRow + (u32)(16 * pr * SH_STRIDE));
                mma16816(oa[2 * pr], P, r0, r1);
                mma16816(oa[2 * pr + 1], P, r2, r3);
            }
        }
        __syncthreads();
    }

    // ---- epilogue: o = O / li ----
    {
        float inv0 = 1.0f / lacc[0];
        float inv1 = 1.0f / lacc[2];
        float* op = d_o + ((size_t)b * NN + q0 + 16 * w) * 256;
#pragma unroll
        for (int j2 = 0; j2 < 32; ++j2) {
            int cc = 8 * j2 + kq;
            *(float2*)(op + (size_t)qr * 256 + cc) =
                make_float2(oa[j2][0] * inv0, oa[j2][1] * inv0);
            *(float2*)(op + (size_t)(qr + 8) * 256 + cc) =
                make_float2(oa[j2][2] * inv1, oa[j2][3] * inv1);
        }
    }
}

// ---------------------------------------------------------------------------
extern "C" void kernel_launch(void* const* d_in, const int* in_sizes, int n_in,
                              void* d_out, int out_size)
{
    const float* x  = (const float*)d_in[0];
    const float* Wf = (const float*)d_in[1];
    const float* bf = (const float*)d_in[2];
    const float* Wg = (const float*)d_in[3];
    const float* bg = (const float*)d_in[4];
    const float* Wh = (const float*)d_in[5];
    const float* bh = (const float*)d_in[6];
    const float* Wv = (const float*)d_in[7];
    const float* bv = (const float*)d_in[8];
    float* out = (float*)d_out;

    cudaFuncSetAttribute(k_fgh,   cudaFuncAttributeMaxDynamicSharedMemorySize, FGH_SMEM);
    cudaFuncSetAttribute(k_vproj, cudaFuncAttributeMaxDynamicSharedMemorySize, VP_SMEM);
    cudaFuncSetAttribute(k_attn,  cudaFuncAttributeMaxDynamicSharedMemorySize, ATTN_SMEM);

    k_fgh<<<256, 320, FGH_SMEM>>>(x, Wh, bh, Wf, bf, Wg, bg);
    k_attn<<<dim3(64, 4), 128, ATTN_SMEM>>>();
    k_vproj<<<256, 256, VP_SMEM>>>(Wv, bv, x, out);
}